// round 2
// baseline (speedup 1.0000x reference)
#include <cuda_runtime.h>
#include <cuda_bf16.h>
#include <math.h>

// ---------------------------------------------------------------------------
// Problem constants
// ---------------------------------------------------------------------------
#define V_  32000
#define D_  512
#define H_  8
#define DFF_ 2048
#define L_  2
#define B_  16
#define LIN_ 400
#define T_  100
#define DEPTH_ 64
#define VEXT_ 32100   // V + max_oov_len(100)
#define SQRT_D 22.627416997969522f

// ---------------------------------------------------------------------------
// Scratch (device globals; no allocations allowed)
// ---------------------------------------------------------------------------
__device__ float g_pe   [LIN_ * D_];
__device__ float g_encx [B_*LIN_ * D_];
__device__ float g_q    [B_*LIN_ * D_];
__device__ float g_k    [B_*LIN_ * D_];
__device__ float g_v    [B_*LIN_ * D_];
__device__ float g_attno[B_*LIN_ * D_];
__device__ float g_tmp  [B_*LIN_ * D_];
__device__ float g_ffn  [B_*LIN_ * DFF_];
__device__ float g_decx [B_*T_ * D_];   // xd (embedding+pe), later dec_out
__device__ float g_o1   [B_*T_ * D_];   // o1 / o2
__device__ float g_embed[B_*T_ * D_];
__device__ float g_block2[B_*H_*T_*LIN_];
__device__ float g_ctx  [B_*T_ * D_];
__device__ float g_pg   [B_*T_];

// ---------------------------------------------------------------------------
// Positional encoding table (f64 angles, matching numpy-f64 reference)
// ---------------------------------------------------------------------------
__global__ void pe_kernel(float* pe) {
    int idx = blockIdx.x * blockDim.x + threadIdx.x;
    if (idx >= LIN_ * D_) return;
    int pos = idx >> 9;
    int d   = idx & (D_ - 1);
    double rate = pow(10000.0, -(double)(2 * (d >> 1)) / (double)D_);
    double ang  = (double)pos * rate;
    pe[idx] = (d & 1) ? (float)cos(ang) : (float)sin(ang);
}

// embedding gather + scale + PE; optionally keep raw embedding (decoder)
__global__ void embed_kernel(const int* __restrict__ tok,
                             const float* __restrict__ emb,
                             const float* __restrict__ pe,
                             float* __restrict__ x,
                             float* __restrict__ raw,
                             int S, int count) {
    int idx = blockIdx.x * blockDim.x + threadIdx.x;
    if (idx >= count) return;
    int d  = idx & (D_ - 1);
    int bs = idx >> 9;
    int s  = bs % S;
    float e = emb[(size_t)tok[bs] * D_ + d];
    if (raw) raw[idx] = e;
    x[idx] = e * SQRT_D + pe[s * D_ + d];
}

// ---------------------------------------------------------------------------
// Generic SGEMM: C[M,N](ldc) = A[M,K] @ W[K,N] + bias, optional ReLU.
// 64x64 tile, BK=16, 4x4 per thread, 256 threads.
// ---------------------------------------------------------------------------
#define BM 64
#define BN 64
#define BK 16
__global__ __launch_bounds__(256) void sgemm_bias(
    const float* __restrict__ A, const float* __restrict__ W,
    const float* __restrict__ bias, float* __restrict__ C,
    int M, int N, int K, int ldc, int relu)
{
    __shared__ float sA[BK][BM + 4];
    __shared__ float sB[BK][BN];
    int tx = threadIdx.x, ty = threadIdx.y;
    int tid = ty * 16 + tx;
    int m0 = blockIdx.y * BM;
    int n0 = blockIdx.x * BN;
    float acc[4][4] = {};
    for (int k0 = 0; k0 < K; k0 += BK) {
        #pragma unroll
        for (int r = 0; r < 4; r++) {
            int idx = tid + r * 256;
            int m = idx >> 4, k = idx & 15;
            sA[k][m] = A[(size_t)(m0 + m) * K + k0 + k];
        }
        #pragma unroll
        for (int r = 0; r < 4; r++) {
            int idx = tid + r * 256;
            int k = idx >> 6, n = idx & 63;
            sB[k][n] = W[(size_t)(k0 + k) * N + n0 + n];
        }
        __syncthreads();
        #pragma unroll
        for (int k = 0; k < BK; k++) {
            float a[4], b[4];
            #pragma unroll
            for (int i = 0; i < 4; i++) a[i] = sA[k][ty * 4 + i];
            #pragma unroll
            for (int j = 0; j < 4; j++) b[j] = sB[k][tx * 4 + j];
            #pragma unroll
            for (int i = 0; i < 4; i++)
                #pragma unroll
                for (int j = 0; j < 4; j++)
                    acc[i][j] += a[i] * b[j];
        }
        __syncthreads();
    }
    #pragma unroll
    for (int i = 0; i < 4; i++) {
        int m = m0 + ty * 4 + i;
        #pragma unroll
        for (int j = 0; j < 4; j++) {
            int n = n0 + tx * 4 + j;
            float vv = acc[i][j] + (bias ? bias[n] : 0.f);
            if (relu) vv = fmaxf(vv, 0.f);
            C[(size_t)m * ldc + n] = vv;
        }
    }
}

// ---------------------------------------------------------------------------
// Fused attention: one block per (b, h, query i).
// scores -> (+mask*-1e9) -> softmax -> P@V. Optionally dump probs (block2).
// mask_mode 0: mask[b, j] (padding, B x Skv)   mode 1: mask[b, i, j]
// ---------------------------------------------------------------------------
__global__ __launch_bounds__(128) void attn_fused(
    const float* __restrict__ Q, const float* __restrict__ Kt,
    const float* __restrict__ Vt, const float* __restrict__ mask,
    int mask_mode, float* __restrict__ Out, float* __restrict__ attn_save,
    int Sq, int Skv)
{
    int blk = blockIdx.x;
    int i = blk % Sq;
    int h = (blk / Sq) % H_;
    int b = blk / (Sq * H_);
    int tid = threadIdx.x;

    __shared__ float qsh[DEPTH_];
    __shared__ float sc[LIN_];
    __shared__ float red[128];

    if (tid < DEPTH_)
        qsh[tid] = Q[((size_t)(b * Sq + i)) * D_ + h * DEPTH_ + tid];
    __syncthreads();

    for (int j = tid; j < Skv; j += 128) {
        const float* kr = Kt + ((size_t)(b * Skv + j)) * D_ + h * DEPTH_;
        float s = 0.f;
        #pragma unroll
        for (int d = 0; d < DEPTH_; d += 4) {
            float4 kv = *(const float4*)(kr + d);
            s += qsh[d] * kv.x + qsh[d+1] * kv.y + qsh[d+2] * kv.z + qsh[d+3] * kv.w;
        }
        s *= 0.125f;
        float mv = (mask_mode == 1) ? mask[((size_t)b * Sq + i) * Skv + j]
                                    : mask[(size_t)b * Skv + j];
        sc[j] = s + mv * -1e9f;
    }
    __syncthreads();

    float m = -INFINITY;
    for (int j = tid; j < Skv; j += 128) m = fmaxf(m, sc[j]);
    red[tid] = m; __syncthreads();
    for (int st = 64; st > 0; st >>= 1) {
        if (tid < st) red[tid] = fmaxf(red[tid], red[tid + st]);
        __syncthreads();
    }
    float mx = red[0];
    __syncthreads();

    float sum = 0.f;
    for (int j = tid; j < Skv; j += 128) {
        float e = expf(sc[j] - mx);
        sc[j] = e;
        sum += e;
    }
    red[tid] = sum; __syncthreads();
    for (int st = 64; st > 0; st >>= 1) {
        if (tid < st) red[tid] += red[tid + st];
        __syncthreads();
    }
    float inv = 1.f / red[0];
    __syncthreads();

    for (int j = tid; j < Skv; j += 128) sc[j] *= inv;
    __syncthreads();

    if (attn_save)
        for (int j = tid; j < Skv; j += 128)
            attn_save[(((size_t)(b * H_ + h) * Sq) + i) * Skv + j] = sc[j];

    if (tid < DEPTH_) {
        float acc = 0.f;
        for (int j = 0; j < Skv; j++)
            acc += sc[j] * Vt[((size_t)(b * Skv + j)) * D_ + h * DEPTH_ + tid];
        Out[((size_t)(b * Sq + i)) * D_ + h * DEPTH_ + tid] = acc;
    }
}

// ---------------------------------------------------------------------------
// y = LayerNorm(x + a) * g + beta   (one block per row of 512)
// ---------------------------------------------------------------------------
__global__ __launch_bounds__(128) void add_ln(
    const float* __restrict__ X, const float* __restrict__ A,
    const float* __restrict__ g, const float* __restrict__ beta,
    float* __restrict__ Y)
{
    int row = blockIdx.x;
    int tid = threadIdx.x;
    __shared__ float red[128];
    size_t base = (size_t)row * D_;
    float v[4];
    float s = 0.f;
    #pragma unroll
    for (int k = 0; k < 4; k++) {
        v[k] = X[base + tid + k * 128] + A[base + tid + k * 128];
        s += v[k];
    }
    red[tid] = s; __syncthreads();
    for (int st = 64; st > 0; st >>= 1) {
        if (tid < st) red[tid] += red[tid + st];
        __syncthreads();
    }
    float mu = red[0] * (1.f / D_);
    __syncthreads();
    float vs = 0.f;
    #pragma unroll
    for (int k = 0; k < 4; k++) { float d = v[k] - mu; vs += d * d; }
    red[tid] = vs; __syncthreads();
    for (int st = 64; st > 0; st >>= 1) {
        if (tid < st) red[tid] += red[tid + st];
        __syncthreads();
    }
    float inv = rsqrtf(red[0] * (1.f / D_) + 1e-6f);
    #pragma unroll
    for (int k = 0; k < 4; k++) {
        int c = tid + k * 128;
        Y[base + c] = (v[k] - mu) * inv * g[c] + beta[c];
    }
}

// context[b,t,h*64+d] = sum_l block2[b,h,t,l] * enc[b,l,h*64+d]
__global__ __launch_bounds__(64) void context_kernel(
    const float* __restrict__ block2, const float* __restrict__ enc,
    float* __restrict__ ctx)
{
    int blk = blockIdx.x;
    int t = blk % T_;
    int h = (blk / T_) % H_;
    int b = blk / (T_ * H_);
    int d = threadIdx.x;
    const float* ar = block2 + ((size_t)(b * H_ + h) * T_ + t) * LIN_;
    float acc = 0.f;
    for (int l = 0; l < LIN_; l++)
        acc += ar[l] * enc[((size_t)(b * LIN_ + l)) * D_ + h * DEPTH_ + d];
    ctx[((size_t)(b * T_ + t)) * D_ + h * DEPTH_ + d] = acc;
}

__global__ __launch_bounds__(128) void pgen_kernel(
    const float* __restrict__ ctx, const float* __restrict__ dec,
    const float* __restrict__ emb, const float* __restrict__ ptrw,
    const float* __restrict__ ptrb, float* __restrict__ pg)
{
    int row = blockIdx.x;
    int tid = threadIdx.x;
    __shared__ float red[128];
    size_t base = (size_t)row * D_;
    float s = 0.f;
    for (int c = tid; c < D_; c += 128)
        s += ctx[base + c] * ptrw[c] + dec[base + c] * ptrw[D_ + c]
           + emb[base + c] * ptrw[2 * D_ + c];
    red[tid] = s; __syncthreads();
    for (int st = 64; st > 0; st >>= 1) {
        if (tid < st) red[tid] += red[tid + st];
        __syncthreads();
    }
    if (tid == 0) {
        float z = red[0] + ptrb[0] + ptrb[1] + ptrb[2];
        pg[row] = 1.f / (1.f + expf(-z));
    }
}

// attn_mean[b,t,l] = mean_h block2[b,h,t,l]
__global__ __launch_bounds__(128) void attn_mean_kernel(
    const float* __restrict__ block2, float* __restrict__ out2)
{
    int row = blockIdx.x;           // b*T + t
    int b = row / T_, t = row % T_;
    for (int l = threadIdx.x; l < LIN_; l += 128) {
        float s = 0.f;
        #pragma unroll
        for (int h = 0; h < H_; h++)
            s += block2[((size_t)(b * H_ + h) * T_ + t) * LIN_ + l];
        out2[(size_t)row * LIN_ + l] = s * 0.125f;
    }
}

__global__ __launch_bounds__(256) void finalize_kernel(
    float* __restrict__ out, const float* __restrict__ pg)
{
    int row = blockIdx.x;
    float p = pg[row];
    size_t base = (size_t)row * VEXT_;
    for (int v = threadIdx.x; v < VEXT_; v += 256)
        out[base + v] = (v < V_) ? p * out[base + v] : 0.f;
}

// serial scatter-add per (b,t) row: deterministic, no atomics
__global__ void scatter_kernel(float* __restrict__ out,
                               const float* __restrict__ am,
                               const float* __restrict__ pg,
                               const int* __restrict__ ext)
{
    int row = blockIdx.x * blockDim.x + threadIdx.x;
    if (row >= B_ * T_) return;
    int b = row / T_;
    float q = 1.f - pg[row];
    float* dst = out + (size_t)row * VEXT_;
    const float* a = am + (size_t)row * LIN_;
    const int* e = ext + (size_t)b * LIN_;
    for (int l = 0; l < LIN_; l++)
        dst[e[l]] += q * a[l];
}

// ---------------------------------------------------------------------------
// Host orchestration
// ---------------------------------------------------------------------------
static inline void gemm(const float* A, const float* W, const float* bias,
                        float* C, int M, int N, int K, int ldc, int relu) {
    dim3 grid(N / BN, M / BM), blk(16, 16);
    sgemm_bias<<<grid, blk>>>(A, W, bias, C, M, N, K, ldc, relu);
}

extern "C" void kernel_launch(void* const* d_in, const int* in_sizes, int n_in,
                              void* d_out, int out_size) {
    const int*   inp     = (const int*)d_in[0];
    const int*   tar     = (const int*)d_in[1];
    const int*   ext     = (const int*)d_in[2];
    const float* enc_pad = (const float*)d_in[3];
    const float* look    = (const float*)d_in[4];
    const float* dec_pad = (const float*)d_in[5];
    int o = (in_sizes[6] <= 4) ? 7 : 6;   // skip max_oov_len if materialized
    const float* emb_enc = (const float*)d_in[o + 0];
    const float* emb_dec = (const float*)d_in[o + 1];
    const float* eaw  = (const float*)d_in[o + 2];
    const float* eab  = (const float*)d_in[o + 3];
    const float* ew1  = (const float*)d_in[o + 4];
    const float* eb1  = (const float*)d_in[o + 5];
    const float* ew2  = (const float*)d_in[o + 6];
    const float* eb2  = (const float*)d_in[o + 7];
    const float* elng = (const float*)d_in[o + 8];
    const float* elnb = (const float*)d_in[o + 9];
    const float* daw  = (const float*)d_in[o + 10];
    const float* dab  = (const float*)d_in[o + 11];
    const float* dw1  = (const float*)d_in[o + 12];
    const float* db1  = (const float*)d_in[o + 13];
    const float* dw2  = (const float*)d_in[o + 14];
    const float* db2  = (const float*)d_in[o + 15];
    const float* dlng = (const float*)d_in[o + 16];
    const float* dlnb = (const float*)d_in[o + 17];
    const float* ptrw = (const float*)d_in[o + 18];
    const float* ptrb = (const float*)d_in[o + 19];
    const float* finw = (const float*)d_in[o + 20];
    const float* finb = (const float*)d_in[o + 21];
    float* out = (float*)d_out;

    float *pe, *encx, *q, *k, *v, *attno, *tmp, *ffn, *decx, *o1buf,
          *embedr, *block2, *ctx, *pg;
    cudaGetSymbolAddress((void**)&pe,     g_pe);
    cudaGetSymbolAddress((void**)&encx,   g_encx);
    cudaGetSymbolAddress((void**)&q,      g_q);
    cudaGetSymbolAddress((void**)&k,      g_k);
    cudaGetSymbolAddress((void**)&v,      g_v);
    cudaGetSymbolAddress((void**)&attno,  g_attno);
    cudaGetSymbolAddress((void**)&tmp,    g_tmp);
    cudaGetSymbolAddress((void**)&ffn,    g_ffn);
    cudaGetSymbolAddress((void**)&decx,   g_decx);
    cudaGetSymbolAddress((void**)&o1buf,  g_o1);
    cudaGetSymbolAddress((void**)&embedr, g_embed);
    cudaGetSymbolAddress((void**)&block2, g_block2);
    cudaGetSymbolAddress((void**)&ctx,    g_ctx);
    cudaGetSymbolAddress((void**)&pg,     g_pg);

    const int ME = B_ * LIN_;  // 6400
    const int MD = B_ * T_;    // 1600

    pe_kernel<<<(LIN_ * D_ + 255) / 256, 256>>>(pe);
    embed_kernel<<<(ME * D_ + 255) / 256, 256>>>(inp, emb_enc, pe, encx,
                                                 nullptr, LIN_, ME * D_);
    embed_kernel<<<(MD * D_ + 255) / 256, 256>>>(tar, emb_dec, pe, decx,
                                                 embedr, T_, MD * D_);

    // ----- encoder (properly chained) -----
    for (int i = 0; i < L_; i++) {
        const float* w  = eaw + (size_t)i * 4 * D_ * D_;
        const float* bb = eab + (size_t)i * 4 * D_;
        gemm(encx, w + 0 * D_ * D_, bb + 0 * D_, q, ME, D_, D_, D_, 0);
        gemm(encx, w + 1 * D_ * D_, bb + 1 * D_, k, ME, D_, D_, D_, 0);
        gemm(encx, w + 2 * D_ * D_, bb + 2 * D_, v, ME, D_, D_, D_, 0);
        attn_fused<<<B_ * H_ * LIN_, 128>>>(q, k, v, enc_pad, 0, attno,
                                            nullptr, LIN_, LIN_);
        gemm(attno, w + 3 * D_ * D_, bb + 3 * D_, tmp, ME, D_, D_, D_, 0);
        add_ln<<<ME, 128>>>(encx, tmp, elng + (size_t)(i * 2 + 0) * D_,
                            elnb + (size_t)(i * 2 + 0) * D_, encx);
        gemm(encx, ew1 + (size_t)i * D_ * DFF_, eb1 + (size_t)i * DFF_,
             ffn, ME, DFF_, D_, DFF_, 1);
        gemm(ffn, ew2 + (size_t)i * DFF_ * D_, eb2 + (size_t)i * D_,
             tmp, ME, D_, DFF_, D_, 0);
        add_ln<<<ME, 128>>>(encx, tmp, elng + (size_t)(i * 2 + 1) * D_,
                            elnb + (size_t)(i * 2 + 1) * D_, encx);
    }

    // ----- decoder: the reference never feeds dec_out back into xd, so only
    // layer L-1 (reading the raw embedded input) affects the outputs. -----
    {
        const int i = L_ - 1;
        // self-attention (causal) on xd
        const float* w0 = daw + (size_t)(i * 2 + 0) * 4 * D_ * D_;
        const float* b0 = dab + (size_t)(i * 2 + 0) * 4 * D_;
        gemm(decx, w0 + 0 * D_ * D_, b0 + 0 * D_, q, MD, D_, D_, D_, 0);
        gemm(decx, w0 + 1 * D_ * D_, b0 + 1 * D_, k, MD, D_, D_, D_, 0);
        gemm(decx, w0 + 2 * D_ * D_, b0 + 2 * D_, v, MD, D_, D_, D_, 0);
        attn_fused<<<B_ * H_ * T_, 128>>>(q, k, v, look, 1, attno,
                                          nullptr, T_, T_);
        gemm(attno, w0 + 3 * D_ * D_, b0 + 3 * D_, tmp, MD, D_, D_, D_, 0);
        add_ln<<<MD, 128>>>(decx, tmp, dlng + (size_t)(i * 3 + 0) * D_,
                            dlnb + (size_t)(i * 3 + 0) * D_, o1buf);
        // cross-attention (kv from encoder output)
        const float* w1 = daw + (size_t)(i * 2 + 1) * 4 * D_ * D_;
        const float* b1 = dab + (size_t)(i * 2 + 1) * 4 * D_;
        gemm(o1buf, w1 + 0 * D_ * D_, b1 + 0 * D_, q, MD, D_, D_, D_, 0);
        gemm(encx, w1 + 1 * D_ * D_, b1 + 1 * D_, k, ME, D_, D_, D_, 0);
        gemm(encx, w1 + 2 * D_ * D_, b1 + 2 * D_, v, ME, D_, D_, D_, 0);
        attn_fused<<<B_ * H_ * T_, 128>>>(q, k, v, dec_pad, 0, attno,
                                          block2, T_, LIN_);
        gemm(attno, w1 + 3 * D_ * D_, b1 + 3 * D_, tmp, MD, D_, D_, D_, 0);
        add_ln<<<MD, 128>>>(o1buf, tmp, dlng + (size_t)(i * 3 + 1) * D_,
                            dlnb + (size_t)(i * 3 + 1) * D_, o1buf);
        // FFN
        gemm(o1buf, dw1 + (size_t)i * D_ * DFF_, db1 + (size_t)i * DFF_,
             ffn, MD, DFF_, D_, DFF_, 1);
        gemm(ffn, dw2 + (size_t)i * DFF_ * D_, db2 + (size_t)i * D_,
             tmp, MD, D_, DFF_, D_, 0);
        add_ln<<<MD, 128>>>(o1buf, tmp, dlng + (size_t)(i * 3 + 2) * D_,
                            dlnb + (size_t)(i * 3 + 2) * D_, decx);
    }

    // ----- head: logits straight into out (row stride VEXT_) -----
    gemm(decx, finw, finb, out, MD, V_, D_, VEXT_, 0);

    float* out2 = out + (size_t)MD * VEXT_;           // attn_mean region
    attn_mean_kernel<<<MD, 128>>>(block2, out2);
    context_kernel<<<B_ * H_ * T_, 64>>>(block2, encx, ctx);
    pgen_kernel<<<MD, 128>>>(ctx, decx, embedr, ptrw, ptrb, pg);
    finalize_kernel<<<MD, 256>>>(out, pg);
    scatter_kernel<<<(MD + 127) / 128, 128>>>(out, out2, pg, ext);
}

// round 9
// speedup vs baseline: 1.8316x; 1.8316x over previous
#include <cuda_runtime.h>
#include <cuda_bf16.h>
#include <math.h>

#define V_  32000
#define D_  512
#define H_  8
#define DFF_ 2048
#define L_  2
#define B_  16
#define LIN_ 400
#define T_  100
#define DEPTH_ 64
#define VEXT_ 32100
#define SQRT_D 22.627416997969522f

// ---------------------------------------------------------------------------
// Scratch
// ---------------------------------------------------------------------------
__device__ __align__(16) float g_pe   [LIN_ * D_];
__device__ __align__(16) float g_encx [B_*LIN_ * D_];
__device__ __align__(16) float g_q    [B_*LIN_ * D_];
__device__ __align__(16) float g_k    [B_*LIN_ * D_];
__device__ __align__(16) float g_v    [B_*LIN_ * D_];
__device__ __align__(16) float g_attno[B_*LIN_ * D_];
__device__ __align__(16) float g_tmp  [B_*LIN_ * D_];
__device__ __align__(16) float g_ffn  [B_*LIN_ * DFF_];
__device__ __align__(16) float g_decx [B_*T_ * D_];
__device__ __align__(16) float g_o1   [B_*T_ * D_];
__device__ __align__(16) float g_embed[B_*T_ * D_];
__device__ __align__(16) float g_block2[B_*H_*T_*LIN_];
__device__ __align__(16) float g_ctx  [B_*T_ * D_];
__device__ float g_pg   [B_*T_];

// ---------------------------------------------------------------------------
__global__ void pe_kernel(float* pe) {
    int idx = blockIdx.x * blockDim.x + threadIdx.x;
    if (idx >= LIN_ * D_) return;
    int pos = idx >> 9;
    int d   = idx & (D_ - 1);
    double rate = pow(10000.0, -(double)(2 * (d >> 1)) / (double)D_);
    double ang  = (double)pos * rate;
    pe[idx] = (d & 1) ? (float)cos(ang) : (float)sin(ang);
}

__global__ void embed_kernel(const int* __restrict__ tok,
                             const float* __restrict__ emb,
                             const float* __restrict__ pe,
                             float* __restrict__ x,
                             float* __restrict__ raw,
                             int S, int count) {
    int idx = blockIdx.x * blockDim.x + threadIdx.x;
    if (idx >= count) return;
    int d  = idx & (D_ - 1);
    int bs = idx >> 9;
    int s  = bs % S;
    float e = emb[(size_t)tok[bs] * D_ + d];
    if (raw) raw[idx] = e;
    x[idx] = e * SQRT_D + pe[s * D_ + d];
}

// ---------------------------------------------------------------------------
// TF32 tensor-core GEMM: C[M,N](ldc) = A[M,K] @ W[K,N] + bias, opt ReLU.
// BM=BN=128, BK=16, 256 threads = 8 warps (4x2), warp tile 32x64,
// mma.sync.m16n8k8.tf32, double-buffered smem.  N,K multiples of 128/16;
// M guarded.
// ---------------------------------------------------------------------------
#define SA_STRIDE 20    // 16 + 4 pad (80B rows: 16B aligned)
#define SB_STRIDE 136   // 128 + 8 pad (544B rows: 16B aligned)

__device__ __forceinline__ float to_tf32(float x) {
    float r;
    asm("cvt.rna.tf32.f32 %0, %1;" : "=f"(r) : "f"(x));
    return r;
}

__global__ __launch_bounds__(256) void gemm_tf32(
    const float* __restrict__ A, const float* __restrict__ W,
    const float* __restrict__ bias, float* __restrict__ C,
    int M, int N, int K, int ldc, int relu)
{
    __shared__ __align__(16) float sA[2][128 * SA_STRIDE];
    __shared__ __align__(16) float sB[2][16 * SB_STRIDE];

    int tid  = threadIdx.x;
    int wid  = tid >> 5;
    int lane = tid & 31;
    int wm = wid >> 1;          // 0..3
    int wn = wid & 1;           // 0..1
    int g  = lane >> 2;         // groupID 0..7
    int tg = lane & 3;          // thread-in-group

    int m0 = blockIdx.y * 128;
    int n0 = blockIdx.x * 128;

    float acc[2][8][4];
    #pragma unroll
    for (int mi = 0; mi < 2; mi++)
        #pragma unroll
        for (int ni = 0; ni < 8; ni++)
            #pragma unroll
            for (int r = 0; r < 4; r++) acc[mi][ni][r] = 0.f;

    int ntiles = K >> 4;
    float4 at[2], bt[2];

    // prologue: load tile 0 into regs then smem buf 0
    {
        #pragma unroll
        for (int r = 0; r < 2; r++) {
            int i = tid + r * 256;
            int row = i >> 2, c4 = (i & 3) * 4;
            if (m0 + row < M)
                at[r] = *(const float4*)(A + (size_t)(m0 + row) * K + c4);
            else at[r] = make_float4(0.f, 0.f, 0.f, 0.f);
        }
        #pragma unroll
        for (int r = 0; r < 2; r++) {
            int i = tid + r * 256;
            int row = i >> 5, c4 = (i & 31) * 4;
            bt[r] = *(const float4*)(W + (size_t)row * N + n0 + c4);
        }
        #pragma unroll
        for (int r = 0; r < 2; r++) {
            int i = tid + r * 256;
            int row = i >> 2, c4 = (i & 3) * 4;
            float4 v = make_float4(to_tf32(at[r].x), to_tf32(at[r].y),
                                   to_tf32(at[r].z), to_tf32(at[r].w));
            *(float4*)(&sA[0][row * SA_STRIDE + c4]) = v;
        }
        #pragma unroll
        for (int r = 0; r < 2; r++) {
            int i = tid + r * 256;
            int row = i >> 5, c4 = (i & 31) * 4;
            float4 v = make_float4(to_tf32(bt[r].x), to_tf32(bt[r].y),
                                   to_tf32(bt[r].z), to_tf32(bt[r].w));
            *(float4*)(&sB[0][row * SB_STRIDE + c4]) = v;
        }
    }
    __syncthreads();

    for (int kt = 0; kt < ntiles; kt++) {
        int cur = kt & 1;
        int nxt = cur ^ 1;
        // prefetch next tile into regs
        if (kt + 1 < ntiles) {
            int k0 = (kt + 1) * 16;
            #pragma unroll
            for (int r = 0; r < 2; r++) {
                int i = tid + r * 256;
                int row = i >> 2, c4 = (i & 3) * 4;
                if (m0 + row < M)
                    at[r] = *(const float4*)(A + (size_t)(m0 + row) * K + k0 + c4);
                else at[r] = make_float4(0.f, 0.f, 0.f, 0.f);
            }
            #pragma unroll
            for (int r = 0; r < 2; r++) {
                int i = tid + r * 256;
                int row = i >> 5, c4 = (i & 31) * 4;
                bt[r] = *(const float4*)(W + (size_t)(k0 + row) * N + n0 + c4);
            }
        }
        // compute on current buffer
        const float* cA = sA[cur];
        const float* cB = sB[cur];
        #pragma unroll
        for (int ks = 0; ks < 16; ks += 8) {
            unsigned af[2][4];
            #pragma unroll
            for (int mi = 0; mi < 2; mi++) {
                int bm = wm * 32 + mi * 16;
                af[mi][0] = __float_as_uint(cA[(bm + g    ) * SA_STRIDE + ks + tg    ]);
                af[mi][1] = __float_as_uint(cA[(bm + g + 8) * SA_STRIDE + ks + tg    ]);
                af[mi][2] = __float_as_uint(cA[(bm + g    ) * SA_STRIDE + ks + tg + 4]);
                af[mi][3] = __float_as_uint(cA[(bm + g + 8) * SA_STRIDE + ks + tg + 4]);
            }
            unsigned bf[8][2];
            #pragma unroll
            for (int ni = 0; ni < 8; ni++) {
                int bn = wn * 64 + ni * 8 + g;
                bf[ni][0] = __float_as_uint(cB[(ks + tg    ) * SB_STRIDE + bn]);
                bf[ni][1] = __float_as_uint(cB[(ks + tg + 4) * SB_STRIDE + bn]);
            }
            #pragma unroll
            for (int mi = 0; mi < 2; mi++)
                #pragma unroll
                for (int ni = 0; ni < 8; ni++) {
                    float* c = acc[mi][ni];
                    asm volatile(
                        "mma.sync.aligned.m16n8k8.row.col.f32.tf32.tf32.f32 "
                        "{%0,%1,%2,%3}, {%4,%5,%6,%7}, {%8,%9}, {%0,%1,%2,%3};\n"
                        : "+f"(c[0]), "+f"(c[1]), "+f"(c[2]), "+f"(c[3])
                        : "r"(af[mi][0]), "r"(af[mi][1]), "r"(af[mi][2]), "r"(af[mi][3]),
                          "r"(bf[ni][0]), "r"(bf[ni][1]));
                }
        }
        // store prefetched into next buffer
        if (kt + 1 < ntiles) {
            #pragma unroll
            for (int r = 0; r < 2; r++) {
                int i = tid + r * 256;
                int row = i >> 2, c4 = (i & 3) * 4;
                float4 v = make_float4(to_tf32(at[r].x), to_tf32(at[r].y),
                                       to_tf32(at[r].z), to_tf32(at[r].w));
                *(float4*)(&sA[nxt][row * SA_STRIDE + c4]) = v;
            }
            #pragma unroll
            for (int r = 0; r < 2; r++) {
                int i = tid + r * 256;
                int row = i >> 5, c4 = (i & 31) * 4;
                float4 v = make_float4(to_tf32(bt[r].x), to_tf32(bt[r].y),
                                       to_tf32(bt[r].z), to_tf32(bt[r].w));
                *(float4*)(&sB[nxt][row * SB_STRIDE + c4]) = v;
            }
            __syncthreads();
        }
    }

    // epilogue
    #pragma unroll
    for (int mi = 0; mi < 2; mi++) {
        int r0 = m0 + wm * 32 + mi * 16 + g;
        int r1 = r0 + 8;
        #pragma unroll
        for (int ni = 0; ni < 8; ni++) {
            int c = n0 + wn * 64 + ni * 8 + 2 * tg;
            float b0 = bias[c], b1 = bias[c + 1];
            float v0 = acc[mi][ni][0] + b0;
            float v1 = acc[mi][ni][1] + b1;
            float v2 = acc[mi][ni][2] + b0;
            float v3 = acc[mi][ni][3] + b1;
            if (relu) {
                v0 = fmaxf(v0, 0.f); v1 = fmaxf(v1, 0.f);
                v2 = fmaxf(v2, 0.f); v3 = fmaxf(v3, 0.f);
            }
            if (r0 < M) { C[(size_t)r0 * ldc + c] = v0; C[(size_t)r0 * ldc + c + 1] = v1; }
            if (r1 < M) { C[(size_t)r1 * ldc + c] = v2; C[(size_t)r1 * ldc + c + 1] = v3; }
        }
    }
}

// ---------------------------------------------------------------------------
// Tiled attention: one block = (b, h, tile of 16 queries). 128 threads.
// scores -> mask -> softmax (warp-parallel) -> P@V.
// Optional: attn_save (probs), and second product P@V2 -> Out2 (context).
// mask_mode 0: mask[b, j]   mode 1: mask[b, i, j]
// ---------------------------------------------------------------------------
#define KV_STRIDE 68   // 64 + 4 pad; 272B rows -> 16B-aligned float4 access
__global__ __launch_bounds__(128) void attn_tiled(
    const float* __restrict__ Q, const float* __restrict__ Kt,
    const float* __restrict__ Vt, const float* __restrict__ mask,
    int mask_mode, float* __restrict__ Out, float* __restrict__ attn_save,
    const float* __restrict__ V2, float* __restrict__ Out2,
    int Sq, int Skv)
{
    int nqt = (Sq + 15) >> 4;
    int qt = blockIdx.x % nqt;
    int h  = (blockIdx.x / nqt) % H_;
    int b  = blockIdx.x / (nqt * H_);
    int i0 = qt * 16;
    int tid = threadIdx.x;
    int wid = tid >> 5;
    int lane = tid & 31;

    __shared__ __align__(16) float sQ[16][64];
    __shared__ __align__(16) float sS[16][LIN_ + 8];
    __shared__ __align__(16) float sKV[64][KV_STRIDE];

    // load Q tile
    #pragma unroll
    for (int r = 0; r < 2; r++) {
        int i = tid + r * 128;
        int row = i >> 4, c4 = (i & 15) * 4;
        float4 v = make_float4(0.f, 0.f, 0.f, 0.f);
        if (i0 + row < Sq)
            v = *(const float4*)(Q + (size_t)(b * Sq + i0 + row) * D_ + h * DEPTH_ + c4);
        *(float4*)(&sQ[row][c4]) = v;
    }
    __syncthreads();

    int nchunks = (Skv + 63) >> 6;
    int myq = tid >> 3;           // 0..15
    int j0  = (tid & 7) * 8;      // 0..56

    // ----- scores -----
    for (int jc = 0; jc < nchunks; jc++) {
        int jbase = jc * 64;
        #pragma unroll
        for (int r = 0; r < 8; r++) {
            int i = tid + r * 128;
            int row = i >> 4, c4 = (i & 15) * 4;
            float4 v = make_float4(0.f, 0.f, 0.f, 0.f);
            if (jbase + row < Skv)
                v = *(const float4*)(Kt + (size_t)(b * Skv + jbase + row) * D_ + h * DEPTH_ + c4);
            *(float4*)(&sKV[row][c4]) = v;
        }
        __syncthreads();
        int iq = i0 + myq; if (iq >= Sq) iq = Sq - 1;   // clamp for mask read
        #pragma unroll
        for (int jj = 0; jj < 8; jj++) {
            int jl = j0 + jj;
            float s = 0.f;
            #pragma unroll
            for (int d = 0; d < 64; d += 4) {
                s += sQ[myq][d    ] * sKV[jl][d    ];
                s += sQ[myq][d + 1] * sKV[jl][d + 1];
                s += sQ[myq][d + 2] * sKV[jl][d + 2];
                s += sQ[myq][d + 3] * sKV[jl][d + 3];
            }
            int j = jbase + jl;
            if (j < Skv) {
                float mv = (mask_mode == 1)
                    ? mask[((size_t)b * Sq + iq) * Skv + j]
                    : mask[(size_t)b * Skv + j];
                sS[myq][j] = s * 0.125f + mv * -1e9f;
            }
        }
        __syncthreads();
    }

    // ----- softmax: warp w handles rows w, w+4, w+8, w+12 -----
    for (int q = wid; q < 16; q += 4) {
        float mx = -INFINITY;
        for (int j = lane; j < Skv; j += 32) mx = fmaxf(mx, sS[q][j]);
        #pragma unroll
        for (int o = 16; o > 0; o >>= 1)
            mx = fmaxf(mx, __shfl_xor_sync(0xffffffff, mx, o));
        float sum = 0.f;
        for (int j = lane; j < Skv; j += 32) {
            float e = expf(sS[q][j] - mx);
            sS[q][j] = e;
            sum += e;
        }
        #pragma unroll
        for (int o = 16; o > 0; o >>= 1)
            sum += __shfl_xor_sync(0xffffffff, sum, o);
        float inv = 1.f / sum;
        for (int j = lane; j < Skv; j += 32) sS[q][j] *= inv;
    }
    __syncthreads();

    // optional probs dump
    if (attn_save && i0 + myq < Sq) {
        size_t base = (((size_t)(b * H_ + h) * Sq) + i0 + myq) * Skv;
        for (int j = (tid & 7); j < Skv; j += 8)
            attn_save[base + j] = sS[myq][j];
    }

    // ----- PV (and optional P@V2) -----
    int d8 = (tid & 7) * 8;
    float acc[8], acc2[8];
    #pragma unroll
    for (int r = 0; r < 8; r++) { acc[r] = 0.f; acc2[r] = 0.f; }

    for (int jc = 0; jc < nchunks; jc++) {
        int jbase = jc * 64;
        int jn = Skv - jbase; if (jn > 64) jn = 64;
        __syncthreads();
        #pragma unroll
        for (int r = 0; r < 8; r++) {
            int i = tid + r * 128;
            int row = i >> 4, c4 = (i & 15) * 4;
            float4 v = make_float4(0.f, 0.f, 0.f, 0.f);
            if (jbase + row < Skv)
                v = *(const float4*)(Vt + (size_t)(b * Skv + jbase + row) * D_ + h * DEPTH_ + c4);
            *(float4*)(&sKV[row][c4]) = v;
        }
        __syncthreads();
        for (int jj = 0; jj < jn; jj++) {
            float p = sS[myq][jbase + jj];
            #pragma unroll
            for (int dd = 0; dd < 8; dd++)
                acc[dd] += p * sKV[jj][d8 + dd];
        }
        if (V2) {
            __syncthreads();
            #pragma unroll
            for (int r = 0; r < 8; r++) {
                int i = tid + r * 128;
                int row = i >> 4, c4 = (i & 15) * 4;
                float4 v = make_float4(0.f, 0.f, 0.f, 0.f);
                if (jbase + row < Skv)
                    v = *(const float4*)(V2 + (size_t)(b * Skv + jbase + row) * D_ + h * DEPTH_ + c4);
                *(float4*)(&sKV[row][c4]) = v;
            }
            __syncthreads();
            for (int jj = 0; jj < jn; jj++) {
                float p = sS[myq][jbase + jj];
                #pragma unroll
                for (int dd = 0; dd < 8; dd++)
                    acc2[dd] += p * sKV[jj][d8 + dd];
            }
        }
    }
    if (i0 + myq < Sq) {
        size_t base = (size_t)(b * Sq + i0 + myq) * D_ + h * DEPTH_ + d8;
        #pragma unroll
        for (int dd = 0; dd < 8; dd++) Out[base + dd] = acc[dd];
        if (Out2)
            #pragma unroll
            for (int dd = 0; dd < 8; dd++) Out2[base + dd] = acc2[dd];
    }
}

// ---------------------------------------------------------------------------
__global__ __launch_bounds__(128) void add_ln(
    const float* __restrict__ X, const float* __restrict__ A,
    const float* __restrict__ g, const float* __restrict__ beta,
    float* __restrict__ Y)
{
    int row = blockIdx.x;
    int tid = threadIdx.x;
    __shared__ float red[128];
    size_t base = (size_t)row * D_;
    float v[4];
    float s = 0.f;
    #pragma unroll
    for (int k = 0; k < 4; k++) {
        v[k] = X[base + tid + k * 128] + A[base + tid + k * 128];
        s += v[k];
    }
    red[tid] = s; __syncthreads();
    for (int st = 64; st > 0; st >>= 1) {
        if (tid < st) red[tid] += red[tid + st];
        __syncthreads();
    }
    float mu = red[0] * (1.f / D_);
    __syncthreads();
    float vs = 0.f;
    #pragma unroll
    for (int k = 0; k < 4; k++) { float d = v[k] - mu; vs += d * d; }
    red[tid] = vs; __syncthreads();
    for (int st = 64; st > 0; st >>= 1) {
        if (tid < st) red[tid] += red[tid + st];
        __syncthreads();
    }
    float inv = rsqrtf(red[0] * (1.f / D_) + 1e-6f);
    #pragma unroll
    for (int k = 0; k < 4; k++) {
        int c = tid + k * 128;
        Y[base + c] = (v[k] - mu) * inv * g[c] + beta[c];
    }
}

__global__ __launch_bounds__(128) void pgen_kernel(
    const float* __restrict__ ctx, const float* __restrict__ dec,
    const float* __restrict__ emb, const float* __restrict__ ptrw,
    const float* __restrict__ ptrb, float* __restrict__ pg)
{
    int row = blockIdx.x;
    int tid = threadIdx.x;
    __shared__ float red[128];
    size_t base = (size_t)row * D_;
    float s = 0.f;
    for (int c = tid; c < D_; c += 128)
        s += ctx[base + c] * ptrw[c] + dec[base + c] * ptrw[D_ + c]
           + emb[base + c] * ptrw[2 * D_ + c];
    red[tid] = s; __syncthreads();
    for (int st = 64; st > 0; st >>= 1) {
        if (tid < st) red[tid] += red[tid + st];
        __syncthreads();
    }
    if (tid == 0) {
        float z = red[0] + ptrb[0] + ptrb[1] + ptrb[2];
        pg[row] = 1.f / (1.f + expf(-z));
    }
}

__global__ __launch_bounds__(128) void attn_mean_kernel(
    const float* __restrict__ block2, float* __restrict__ out2)
{
    int row = blockIdx.x;
    int b = row / T_, t = row % T_;
    for (int l = threadIdx.x; l < LIN_; l += 128) {
        float s = 0.f;
        #pragma unroll
        for (int h = 0; h < H_; h++)
            s += block2[((size_t)(b * H_ + h) * T_ + t) * LIN_ + l];
        out2[(size_t)row * LIN_ + l] = s * 0.125f;
    }
}

__global__ __launch_bounds__(256) void finalize_kernel(
    float* __restrict__ out, const float* __restrict__ pg)
{
    int row = blockIdx.x;
    float p = pg[row];
    size_t base = (size_t)row * VEXT_;
    for (int v = threadIdx.x; v < VEXT_; v += 256)
        out[base + v] = (v < V_) ? p * out[base + v] : 0.f;
}

__global__ void scatter_kernel(float* __restrict__ out,
                               const float* __restrict__ am,
                               const float* __restrict__ pg,
                               const int* __restrict__ ext)
{
    int idx = blockIdx.x * blockDim.x + threadIdx.x;
    if (idx >= B_ * T_ * LIN_) return;
    int l = idx % LIN_;
    int row = idx / LIN_;
    int b = row / T_;
    float q = 1.f - pg[row];
    atomicAdd(&out[(size_t)row * VEXT_ + ext[(size_t)b * LIN_ + l]],
              q * am[(size_t)row * LIN_ + l]);
}

// ---------------------------------------------------------------------------
static inline void gemm(const float* A, const float* W, const float* bias,
                        float* C, int M, int N, int K, int ldc, int relu) {
    dim3 grid(N / 128, (M + 127) / 128);
    gemm_tf32<<<grid, 256>>>(A, W, bias, C, M, N, K, ldc, relu);
}

extern "C" void kernel_launch(void* const* d_in, const int* in_sizes, int n_in,
                              void* d_out, int out_size) {
    const int*   inp     = (const int*)d_in[0];
    const int*   tar     = (const int*)d_in[1];
    const int*   ext     = (const int*)d_in[2];
    const float* enc_pad = (const float*)d_in[3];
    const float* look    = (const float*)d_in[4];
    const float* dec_pad = (const float*)d_in[5];
    int o = (in_sizes[6] <= 4) ? 7 : 6;
    const float* emb_enc = (const float*)d_in[o + 0];
    const float* emb_dec = (const float*)d_in[o + 1];
    const float* eaw  = (const float*)d_in[o + 2];
    const float* eab  = (const float*)d_in[o + 3];
    const float* ew1  = (const float*)d_in[o + 4];
    const float* eb1  = (const float*)d_in[o + 5];
    const float* ew2  = (const float*)d_in[o + 6];
    const float* eb2  = (const float*)d_in[o + 7];
    const float* elng = (const float*)d_in[o + 8];
    const float* elnb = (const float*)d_in[o + 9];
    const float* daw  = (const float*)d_in[o + 10];
    const float* dab  = (const float*)d_in[o + 11];
    const float* dw1  = (const float*)d_in[o + 12];
    const float* db1  = (const float*)d_in[o + 13];
    const float* dw2  = (const float*)d_in[o + 14];
    const float* db2  = (const float*)d_in[o + 15];
    const float* dlng = (const float*)d_in[o + 16];
    const float* dlnb = (const float*)d_in[o + 17];
    const float* ptrw = (const float*)d_in[o + 18];
    const float* ptrb = (const float*)d_in[o + 19];
    const float* finw = (const float*)d_in[o + 20];
    const float* finb = (const float*)d_in[o + 21];
    float* out = (float*)d_out;

    float *pe, *encx, *q, *k, *v, *attno, *tmp, *ffn, *decx, *o1buf,
          *embedr, *block2, *ctx, *pg;
    cudaGetSymbolAddress((void**)&pe,     g_pe);
    cudaGetSymbolAddress((void**)&encx,   g_encx);
    cudaGetSymbolAddress((void**)&q,      g_q);
    cudaGetSymbolAddress((void**)&k,      g_k);
    cudaGetSymbolAddress((void**)&v,      g_v);
    cudaGetSymbolAddress((void**)&attno,  g_attno);
    cudaGetSymbolAddress((void**)&tmp,    g_tmp);
    cudaGetSymbolAddress((void**)&ffn,    g_ffn);
    cudaGetSymbolAddress((void**)&decx,   g_decx);
    cudaGetSymbolAddress((void**)&o1buf,  g_o1);
    cudaGetSymbolAddress((void**)&embedr, g_embed);
    cudaGetSymbolAddress((void**)&block2, g_block2);
    cudaGetSymbolAddress((void**)&ctx,    g_ctx);
    cudaGetSymbolAddress((void**)&pg,     g_pg);

    const int ME = B_ * LIN_;  // 6400
    const int MD = B_ * T_;    // 1600

    pe_kernel<<<(LIN_ * D_ + 255) / 256, 256>>>(pe);
    embed_kernel<<<(ME * D_ + 255) / 256, 256>>>(inp, emb_enc, pe, encx,
                                                 nullptr, LIN_, ME * D_);
    embed_kernel<<<(MD * D_ + 255) / 256, 256>>>(tar, emb_dec, pe, decx,
                                                 embedr, T_, MD * D_);

    // ----- encoder -----
    for (int i = 0; i < L_; i++) {
        const float* w  = eaw + (size_t)i * 4 * D_ * D_;
        const float* bb = eab + (size_t)i * 4 * D_;
        gemm(encx, w + 0 * D_ * D_, bb + 0 * D_, q, ME, D_, D_, D_, 0);
        gemm(encx, w + 1 * D_ * D_, bb + 1 * D_, k, ME, D_, D_, D_, 0);
        gemm(encx, w + 2 * D_ * D_, bb + 2 * D_, v, ME, D_, D_, D_, 0);
        attn_tiled<<<B_ * H_ * ((LIN_ + 15) / 16), 128>>>(
            q, k, v, enc_pad, 0, attno, nullptr, nullptr, nullptr, LIN_, LIN_);
        gemm(attno, w + 3 * D_ * D_, bb + 3 * D_, tmp, ME, D_, D_, D_, 0);
        add_ln<<<ME, 128>>>(encx, tmp, elng + (size_t)(i * 2 + 0) * D_,
                            elnb + (size_t)(i * 2 + 0) * D_, encx);
        gemm(encx, ew1 + (size_t)i * D_ * DFF_, eb1 + (size_t)i * DFF_,
             ffn, ME, DFF_, D_, DFF_, 1);
        gemm(ffn, ew2 + (size_t)i * DFF_ * D_, eb2 + (size_t)i * D_,
             tmp, ME, D_, DFF_, D_, 0);
        add_ln<<<ME, 128>>>(encx, tmp, elng + (size_t)(i * 2 + 1) * D_,
                            elnb + (size_t)(i * 2 + 1) * D_, encx);
    }

    // ----- decoder: only layer L-1 affects outputs (reference never feeds
    // dec_out back into xd) -----
    {
        const int i = L_ - 1;
        const float* w0 = daw + (size_t)(i * 2 + 0) * 4 * D_ * D_;
        const float* b0 = dab + (size_t)(i * 2 + 0) * 4 * D_;
        gemm(decx, w0 + 0 * D_ * D_, b0 + 0 * D_, q, MD, D_, D_, D_, 0);
        gemm(decx, w0 + 1 * D_ * D_, b0 + 1 * D_, k, MD, D_, D_, D_, 0);
        gemm(decx, w0 + 2 * D_ * D_, b0 + 2 * D_, v, MD, D_, D_, D_, 0);
        attn_tiled<<<B_ * H_ * ((T_ + 15) / 16), 128>>>(
            q, k, v, look, 1, attno, nullptr, nullptr, nullptr, T_, T_);
        gemm(attno, w0 + 3 * D_ * D_, b0 + 3 * D_, tmp, MD, D_, D_, D_, 0);
        add_ln<<<MD, 128>>>(decx, tmp, dlng + (size_t)(i * 3 + 0) * D_,
                            dlnb + (size_t)(i * 3 + 0) * D_, o1buf);
        // cross-attention; also fuses context = P @ enc_heads
        const float* w1 = daw + (size_t)(i * 2 + 1) * 4 * D_ * D_;
        const float* b1 = dab + (size_t)(i * 2 + 1) * 4 * D_;
        gemm(o1buf, w1 + 0 * D_ * D_, b1 + 0 * D_, q, MD, D_, D_, D_, 0);
        gemm(encx, w1 + 1 * D_ * D_, b1 + 1 * D_, k, ME, D_, D_, D_, 0);
        gemm(encx, w1 + 2 * D_ * D_, b1 + 2 * D_, v, ME, D_, D_, D_, 0);
        attn_tiled<<<B_ * H_ * ((T_ + 15) / 16), 128>>>(
            q, k, v, dec_pad, 0, attno, block2, encx, ctx, T_, LIN_);
        gemm(attno, w1 + 3 * D_ * D_, b1 + 3 * D_, tmp, MD, D_, D_, D_, 0);
        add_ln<<<MD, 128>>>(o1buf, tmp, dlng + (size_t)(i * 3 + 1) * D_,
                            dlnb + (size_t)(i * 3 + 1) * D_, o1buf);
        gemm(o1buf, dw1 + (size_t)i * D_ * DFF_, db1 + (size_t)i * DFF_,
             ffn, MD, DFF_, D_, DFF_, 1);
        gemm(ffn, dw2 + (size_t)i * DFF_ * D_, db2 + (size_t)i * D_,
             tmp, MD, D_, DFF_, D_, 0);
        add_ln<<<MD, 128>>>(o1buf, tmp, dlng + (size_t)(i * 3 + 2) * D_,
                            dlnb + (size_t)(i * 3 + 2) * D_, decx);
    }

    // ----- head -----
    gemm(decx, finw, finb, out, MD, V_, D_, VEXT_, 0);

    float* out2 = out + (size_t)MD * VEXT_;
    attn_mean_kernel<<<MD, 128>>>(block2, out2);
    pgen_kernel<<<MD, 128>>>(ctx, decx, embedr, ptrw, ptrb, pg);
    finalize_kernel<<<MD, 256>>>(out, pg);
    scatter_kernel<<<(B_ * T_ * LIN_ + 255) / 256, 256>>>(out, out2, pg, ext);
}

// round 10
// speedup vs baseline: 3.3528x; 1.8305x over previous
#include <cuda_runtime.h>
#include <cuda_bf16.h>
#include <math.h>

#define V_  32000
#define D_  512
#define H_  8
#define DFF_ 2048
#define L_  2
#define B_  16
#define LIN_ 400
#define T_  100
#define DEPTH_ 64
#define VEXT_ 32100
#define SQRT_D 22.627416997969522f

// ---------------------------------------------------------------------------
// Scratch
// ---------------------------------------------------------------------------
__device__ __align__(16) float g_pe   [LIN_ * D_];
__device__ __align__(16) float g_encx [B_*LIN_ * D_];
__device__ __align__(16) float g_q    [B_*LIN_ * D_];
__device__ __align__(16) float g_k    [B_*LIN_ * D_];
__device__ __align__(16) float g_v    [B_*LIN_ * D_];
__device__ __align__(16) float g_attno[B_*LIN_ * D_];
__device__ __align__(16) float g_tmp  [B_*LIN_ * D_];
__device__ __align__(16) float g_ffn  [B_*LIN_ * DFF_];
__device__ __align__(16) float g_decx [B_*T_ * D_];
__device__ __align__(16) float g_o1   [B_*T_ * D_];
__device__ __align__(16) float g_embed[B_*T_ * D_];
__device__ __align__(16) float g_block2[B_*H_*T_*LIN_];
__device__ __align__(16) float g_ctx  [B_*T_ * D_];
__device__ float g_pg   [B_*T_];

// ---------------------------------------------------------------------------
__global__ void pe_kernel(float* pe) {
    int idx = blockIdx.x * blockDim.x + threadIdx.x;
    if (idx >= LIN_ * D_) return;
    int pos = idx >> 9;
    int d   = idx & (D_ - 1);
    double rate = pow(10000.0, -(double)(2 * (d >> 1)) / (double)D_);
    double ang  = (double)pos * rate;
    pe[idx] = (d & 1) ? (float)cos(ang) : (float)sin(ang);
}

__global__ void embed_kernel(const int* __restrict__ tok,
                             const float* __restrict__ emb,
                             const float* __restrict__ pe,
                             float* __restrict__ x,
                             float* __restrict__ raw,
                             int S, int count) {
    int idx = blockIdx.x * blockDim.x + threadIdx.x;
    if (idx >= count) return;
    int d  = idx & (D_ - 1);
    int bs = idx >> 9;
    int s  = bs % S;
    float e = emb[(size_t)tok[bs] * D_ + d];
    if (raw) raw[idx] = e;
    x[idx] = e * SQRT_D + pe[s * D_ + d];
}

// ---------------------------------------------------------------------------
// TF32 tensor-core GEMM: C[M,N](ldc) = rowscale * (A[M,K] @ W[K,N] + bias).
// Template WMW = warps along M (4 -> BM=128, 2 -> BM=64). 256 threads.
// BK=16, mma.sync.m16n8k8.tf32, double-buffered smem + register prefetch.
// ---------------------------------------------------------------------------
#define SA_STRIDE 20    // 16 + 4 pad (80B rows: 16B aligned)
#define SB_STRIDE 136   // 128 + 8 pad (544B rows: 16B aligned)

__device__ __forceinline__ float to_tf32(float x) {
    float r;
    asm("cvt.rna.tf32.f32 %0, %1;" : "=f"(r) : "f"(x));
    return r;
}

template<int WMW>
__global__ __launch_bounds__(256) void gemm_tf32(
    const float* __restrict__ A, const float* __restrict__ W,
    const float* __restrict__ bias, const float* __restrict__ rowscale,
    float* __restrict__ C,
    int M, int N, int K, int ldc, int relu)
{
    constexpr int WNW = 8 / WMW;          // warps along N: 2 or 4
    constexpr int BMt = WMW * 32;         // 128 or 64
    constexpr int NI  = 128 / (WNW * 8);  // 8 or 4 (n-frags per warp)
    constexpr int AR  = BMt / 64;         // A float4 loads per thread: 2 or 1

    __shared__ __align__(16) float sA[2][BMt * SA_STRIDE];
    __shared__ __align__(16) float sB[2][16 * SB_STRIDE];

    int tid  = threadIdx.x;
    int wid  = tid >> 5;
    int lane = tid & 31;
    int wm = wid / WNW;
    int wn = wid % WNW;
    int g  = lane >> 2;
    int tg = lane & 3;

    int m0 = blockIdx.y * BMt;
    int n0 = blockIdx.x * 128;

    float acc[2][NI][4];
    #pragma unroll
    for (int mi = 0; mi < 2; mi++)
        #pragma unroll
        for (int ni = 0; ni < NI; ni++)
            #pragma unroll
            for (int r = 0; r < 4; r++) acc[mi][ni][r] = 0.f;

    int ntiles = K >> 4;
    float4 at[AR], bt[2];

    // prologue
    {
        #pragma unroll
        for (int r = 0; r < AR; r++) {
            int i = tid + r * 256;
            int row = i >> 2, c4 = (i & 3) * 4;
            if (m0 + row < M)
                at[r] = *(const float4*)(A + (size_t)(m0 + row) * K + c4);
            else at[r] = make_float4(0.f, 0.f, 0.f, 0.f);
        }
        #pragma unroll
        for (int r = 0; r < 2; r++) {
            int i = tid + r * 256;
            int row = i >> 5, c4 = (i & 31) * 4;
            bt[r] = *(const float4*)(W + (size_t)row * N + n0 + c4);
        }
        #pragma unroll
        for (int r = 0; r < AR; r++) {
            int i = tid + r * 256;
            int row = i >> 2, c4 = (i & 3) * 4;
            float4 v = make_float4(to_tf32(at[r].x), to_tf32(at[r].y),
                                   to_tf32(at[r].z), to_tf32(at[r].w));
            *(float4*)(&sA[0][row * SA_STRIDE + c4]) = v;
        }
        #pragma unroll
        for (int r = 0; r < 2; r++) {
            int i = tid + r * 256;
            int row = i >> 5, c4 = (i & 31) * 4;
            float4 v = make_float4(to_tf32(bt[r].x), to_tf32(bt[r].y),
                                   to_tf32(bt[r].z), to_tf32(bt[r].w));
            *(float4*)(&sB[0][row * SB_STRIDE + c4]) = v;
        }
    }
    __syncthreads();

    for (int kt = 0; kt < ntiles; kt++) {
        int cur = kt & 1;
        int nxt = cur ^ 1;
        if (kt + 1 < ntiles) {
            int k0 = (kt + 1) * 16;
            #pragma unroll
            for (int r = 0; r < AR; r++) {
                int i = tid + r * 256;
                int row = i >> 2, c4 = (i & 3) * 4;
                if (m0 + row < M)
                    at[r] = *(const float4*)(A + (size_t)(m0 + row) * K + k0 + c4);
                else at[r] = make_float4(0.f, 0.f, 0.f, 0.f);
            }
            #pragma unroll
            for (int r = 0; r < 2; r++) {
                int i = tid + r * 256;
                int row = i >> 5, c4 = (i & 31) * 4;
                bt[r] = *(const float4*)(W + (size_t)(k0 + row) * N + n0 + c4);
            }
        }
        const float* cA = sA[cur];
        const float* cB = sB[cur];
        #pragma unroll
        for (int ks = 0; ks < 16; ks += 8) {
            unsigned af[2][4];
            #pragma unroll
            for (int mi = 0; mi < 2; mi++) {
                int bm = wm * 32 + mi * 16;
                af[mi][0] = __float_as_uint(cA[(bm + g    ) * SA_STRIDE + ks + tg    ]);
                af[mi][1] = __float_as_uint(cA[(bm + g + 8) * SA_STRIDE + ks + tg    ]);
                af[mi][2] = __float_as_uint(cA[(bm + g    ) * SA_STRIDE + ks + tg + 4]);
                af[mi][3] = __float_as_uint(cA[(bm + g + 8) * SA_STRIDE + ks + tg + 4]);
            }
            unsigned bf[NI][2];
            #pragma unroll
            for (int ni = 0; ni < NI; ni++) {
                int bn = wn * (NI * 8) + ni * 8 + g;
                bf[ni][0] = __float_as_uint(cB[(ks + tg    ) * SB_STRIDE + bn]);
                bf[ni][1] = __float_as_uint(cB[(ks + tg + 4) * SB_STRIDE + bn]);
            }
            #pragma unroll
            for (int mi = 0; mi < 2; mi++)
                #pragma unroll
                for (int ni = 0; ni < NI; ni++) {
                    float* c = acc[mi][ni];
                    asm volatile(
                        "mma.sync.aligned.m16n8k8.row.col.f32.tf32.tf32.f32 "
                        "{%0,%1,%2,%3}, {%4,%5,%6,%7}, {%8,%9}, {%0,%1,%2,%3};\n"
                        : "+f"(c[0]), "+f"(c[1]), "+f"(c[2]), "+f"(c[3])
                        : "r"(af[mi][0]), "r"(af[mi][1]), "r"(af[mi][2]), "r"(af[mi][3]),
                          "r"(bf[ni][0]), "r"(bf[ni][1]));
                }
        }
        if (kt + 1 < ntiles) {
            #pragma unroll
            for (int r = 0; r < AR; r++) {
                int i = tid + r * 256;
                int row = i >> 2, c4 = (i & 3) * 4;
                float4 v = make_float4(to_tf32(at[r].x), to_tf32(at[r].y),
                                       to_tf32(at[r].z), to_tf32(at[r].w));
                *(float4*)(&sA[nxt][row * SA_STRIDE + c4]) = v;
            }
            #pragma unroll
            for (int r = 0; r < 2; r++) {
                int i = tid + r * 256;
                int row = i >> 5, c4 = (i & 31) * 4;
                float4 v = make_float4(to_tf32(bt[r].x), to_tf32(bt[r].y),
                                       to_tf32(bt[r].z), to_tf32(bt[r].w));
                *(float4*)(&sB[nxt][row * SB_STRIDE + c4]) = v;
            }
            __syncthreads();
        }
    }

    // epilogue
    #pragma unroll
    for (int mi = 0; mi < 2; mi++) {
        int r0 = m0 + wm * 32 + mi * 16 + g;
        int r1 = r0 + 8;
        float rs0 = 1.f, rs1 = 1.f;
        if (rowscale) {
            if (r0 < M) rs0 = rowscale[r0];
            if (r1 < M) rs1 = rowscale[r1];
        }
        #pragma unroll
        for (int ni = 0; ni < NI; ni++) {
            int c = n0 + wn * (NI * 8) + ni * 8 + 2 * tg;
            float b0 = bias[c], b1 = bias[c + 1];
            float v0 = (acc[mi][ni][0] + b0) * rs0;
            float v1 = (acc[mi][ni][1] + b1) * rs0;
            float v2 = (acc[mi][ni][2] + b0) * rs1;
            float v3 = (acc[mi][ni][3] + b1) * rs1;
            if (relu) {
                v0 = fmaxf(v0, 0.f); v1 = fmaxf(v1, 0.f);
                v2 = fmaxf(v2, 0.f); v3 = fmaxf(v3, 0.f);
            }
            if (r0 < M) { C[(size_t)r0 * ldc + c] = v0; C[(size_t)r0 * ldc + c + 1] = v1; }
            if (r1 < M) { C[(size_t)r1 * ldc + c] = v2; C[(size_t)r1 * ldc + c + 1] = v3; }
        }
    }
}

// ---------------------------------------------------------------------------
// Tiled attention: one block = (b, h, tile of 16 queries). 128 threads.
// Conflict-free scores: thread (myq=tid>>3, jt=tid&7) covers j = jt + 8*jj.
// mask_mode 0: mask[b, j]   mode 1: mask[b, i, j]
// ---------------------------------------------------------------------------
#define KV_STRIDE 68   // 272B rows: float4-aligned; row step = 4 banks
#define Q_STRIDE  68
__global__ __launch_bounds__(128) void attn_tiled(
    const float* __restrict__ Q, const float* __restrict__ Kt,
    const float* __restrict__ Vt, const float* __restrict__ mask,
    int mask_mode, float* __restrict__ Out, float* __restrict__ attn_save,
    const float* __restrict__ V2, float* __restrict__ Out2,
    int Sq, int Skv)
{
    int nqt = (Sq + 15) >> 4;
    int qt = blockIdx.x % nqt;
    int h  = (blockIdx.x / nqt) % H_;
    int b  = blockIdx.x / (nqt * H_);
    int i0 = qt * 16;
    int tid = threadIdx.x;
    int wid = tid >> 5;
    int lane = tid & 31;

    __shared__ __align__(16) float sQ[16][Q_STRIDE];
    __shared__ __align__(16) float sS[16][LIN_ + 8];
    __shared__ __align__(16) float sKV[64][KV_STRIDE];

    // load Q tile
    #pragma unroll
    for (int r = 0; r < 2; r++) {
        int i = tid + r * 128;
        int row = i >> 4, c4 = (i & 15) * 4;
        float4 v = make_float4(0.f, 0.f, 0.f, 0.f);
        if (i0 + row < Sq)
            v = *(const float4*)(Q + (size_t)(b * Sq + i0 + row) * D_ + h * DEPTH_ + c4);
        *(float4*)(&sQ[row][c4]) = v;
    }
    __syncthreads();

    int nchunks = (Skv + 63) >> 6;
    int myq = tid >> 3;           // 0..15
    int jt  = tid & 7;            // 0..7

    // ----- scores (conflict-free, q hoisted) -----
    for (int jc = 0; jc < nchunks; jc++) {
        int jbase = jc * 64;
        #pragma unroll
        for (int r = 0; r < 8; r++) {
            int i = tid + r * 128;
            int row = i >> 4, c4 = (i & 15) * 4;
            float4 v = make_float4(0.f, 0.f, 0.f, 0.f);
            if (jbase + row < Skv)
                v = *(const float4*)(Kt + (size_t)(b * Skv + jbase + row) * D_ + h * DEPTH_ + c4);
            *(float4*)(&sKV[row][c4]) = v;
        }
        __syncthreads();
        float qacc[8];
        #pragma unroll
        for (int jj = 0; jj < 8; jj++) qacc[jj] = 0.f;
        #pragma unroll 4
        for (int d = 0; d < 64; d++) {
            float qd = sQ[myq][d];
            #pragma unroll
            for (int jj = 0; jj < 8; jj++)
                qacc[jj] += qd * sKV[jt + 8 * jj][d];
        }
        int iq = i0 + myq; if (iq >= Sq) iq = Sq - 1;
        #pragma unroll
        for (int jj = 0; jj < 8; jj++) {
            int j = jbase + jt + 8 * jj;
            if (j < Skv) {
                float mv = (mask_mode == 1)
                    ? mask[((size_t)b * Sq + iq) * Skv + j]
                    : mask[(size_t)b * Skv + j];
                sS[myq][j] = qacc[jj] * 0.125f + mv * -1e9f;
            }
        }
        __syncthreads();
    }

    // ----- softmax: warp w handles rows w, w+4, w+8, w+12 -----
    for (int q = wid; q < 16; q += 4) {
        float mx = -INFINITY;
        for (int j = lane; j < Skv; j += 32) mx = fmaxf(mx, sS[q][j]);
        #pragma unroll
        for (int o = 16; o > 0; o >>= 1)
            mx = fmaxf(mx, __shfl_xor_sync(0xffffffff, mx, o));
        float sum = 0.f;
        for (int j = lane; j < Skv; j += 32) {
            float e = expf(sS[q][j] - mx);
            sS[q][j] = e;
            sum += e;
        }
        #pragma unroll
        for (int o = 16; o > 0; o >>= 1)
            sum += __shfl_xor_sync(0xffffffff, sum, o);
        float inv = 1.f / sum;
        for (int j = lane; j < Skv; j += 32) sS[q][j] *= inv;
    }
    __syncthreads();

    // optional probs dump
    if (attn_save && i0 + myq < Sq) {
        size_t base = (((size_t)(b * H_ + h) * Sq) + i0 + myq) * Skv;
        for (int j = jt; j < Skv; j += 8)
            attn_save[base + j] = sS[myq][j];
    }

    // ----- PV (and optional P@V2) -----
    int d8 = jt * 8;
    float acc[8], acc2[8];
    #pragma unroll
    for (int r = 0; r < 8; r++) { acc[r] = 0.f; acc2[r] = 0.f; }

    for (int jc = 0; jc < nchunks; jc++) {
        int jbase = jc * 64;
        int jn = Skv - jbase; if (jn > 64) jn = 64;
        __syncthreads();
        #pragma unroll
        for (int r = 0; r < 8; r++) {
            int i = tid + r * 128;
            int row = i >> 4, c4 = (i & 15) * 4;
            float4 v = make_float4(0.f, 0.f, 0.f, 0.f);
            if (jbase + row < Skv)
                v = *(const float4*)(Vt + (size_t)(b * Skv + jbase + row) * D_ + h * DEPTH_ + c4);
            *(float4*)(&sKV[row][c4]) = v;
        }
        __syncthreads();
        for (int jj = 0; jj < jn; jj++) {
            float p = sS[myq][jbase + jj];
            #pragma unroll
            for (int dd = 0; dd < 8; dd++)
                acc[dd] += p * sKV[jj][d8 + dd];
        }
        if (V2) {
            __syncthreads();
            #pragma unroll
            for (int r = 0; r < 8; r++) {
                int i = tid + r * 128;
                int row = i >> 4, c4 = (i & 15) * 4;
                float4 v = make_float4(0.f, 0.f, 0.f, 0.f);
                if (jbase + row < Skv)
                    v = *(const float4*)(V2 + (size_t)(b * Skv + jbase + row) * D_ + h * DEPTH_ + c4);
                *(float4*)(&sKV[row][c4]) = v;
            }
            __syncthreads();
            for (int jj = 0; jj < jn; jj++) {
                float p = sS[myq][jbase + jj];
                #pragma unroll
                for (int dd = 0; dd < 8; dd++)
                    acc2[dd] += p * sKV[jj][d8 + dd];
            }
        }
    }
    if (i0 + myq < Sq) {
        size_t base = (size_t)(b * Sq + i0 + myq) * D_ + h * DEPTH_ + d8;
        #pragma unroll
        for (int dd = 0; dd < 8; dd++) Out[base + dd] = acc[dd];
        if (Out2)
            #pragma unroll
            for (int dd = 0; dd < 8; dd++) Out2[base + dd] = acc2[dd];
    }
}

// ---------------------------------------------------------------------------
__global__ __launch_bounds__(128) void add_ln(
    const float* __restrict__ X, const float* __restrict__ A,
    const float* __restrict__ g, const float* __restrict__ beta,
    float* __restrict__ Y)
{
    int row = blockIdx.x;
    int tid = threadIdx.x;
    __shared__ float red[128];
    size_t base = (size_t)row * D_;
    float v[4];
    float s = 0.f;
    #pragma unroll
    for (int k = 0; k < 4; k++) {
        v[k] = X[base + tid + k * 128] + A[base + tid + k * 128];
        s += v[k];
    }
    red[tid] = s; __syncthreads();
    for (int st = 64; st > 0; st >>= 1) {
        if (tid < st) red[tid] += red[tid + st];
        __syncthreads();
    }
    float mu = red[0] * (1.f / D_);
    __syncthreads();
    float vs = 0.f;
    #pragma unroll
    for (int k = 0; k < 4; k++) { float d = v[k] - mu; vs += d * d; }
    red[tid] = vs; __syncthreads();
    for (int st = 64; st > 0; st >>= 1) {
        if (tid < st) red[tid] += red[tid + st];
        __syncthreads();
    }
    float inv = rsqrtf(red[0] * (1.f / D_) + 1e-6f);
    #pragma unroll
    for (int k = 0; k < 4; k++) {
        int c = tid + k * 128;
        Y[base + c] = (v[k] - mu) * inv * g[c] + beta[c];
    }
}

__global__ __launch_bounds__(128) void pgen_kernel(
    const float* __restrict__ ctx, const float* __restrict__ dec,
    const float* __restrict__ emb, const float* __restrict__ ptrw,
    const float* __restrict__ ptrb, float* __restrict__ pg)
{
    int row = blockIdx.x;
    int tid = threadIdx.x;
    __shared__ float red[128];
    size_t base = (size_t)row * D_;
    float s = 0.f;
    for (int c = tid; c < D_; c += 128)
        s += ctx[base + c] * ptrw[c] + dec[base + c] * ptrw[D_ + c]
           + emb[base + c] * ptrw[2 * D_ + c];
    red[tid] = s; __syncthreads();
    for (int st = 64; st > 0; st >>= 1) {
        if (tid < st) red[tid] += red[tid + st];
        __syncthreads();
    }
    if (tid == 0) {
        float z = red[0] + ptrb[0] + ptrb[1] + ptrb[2];
        pg[row] = 1.f / (1.f + expf(-z));
    }
}

__global__ __launch_bounds__(128) void attn_mean_kernel(
    const float* __restrict__ block2, float* __restrict__ out2)
{
    int row = blockIdx.x;
    int b = row / T_, t = row % T_;
    for (int l = threadIdx.x; l < LIN_; l += 128) {
        float s = 0.f;
        #pragma unroll
        for (int h = 0; h < H_; h++)
            s += block2[((size_t)(b * H_ + h) * T_ + t) * LIN_ + l];
        out2[(size_t)row * LIN_ + l] = s * 0.125f;
    }
}

// zero the 100 OOV tail columns of each logits row
__global__ void zero_tail_kernel(float* __restrict__ out) {
    int idx = blockIdx.x * blockDim.x + threadIdx.x;
    if (idx >= B_ * T_ * 100) return;
    int row = idx / 100;
    int t   = idx % 100;
    out[(size_t)row * VEXT_ + V_ + t] = 0.f;
}

__global__ void scatter_kernel(float* __restrict__ out,
                               const float* __restrict__ am,
                               const float* __restrict__ pg,
                               const int* __restrict__ ext)
{
    int idx = blockIdx.x * blockDim.x + threadIdx.x;
    if (idx >= B_ * T_ * LIN_) return;
    int l = idx % LIN_;
    int row = idx / LIN_;
    int b = row / T_;
    float q = 1.f - pg[row];
    atomicAdd(&out[(size_t)row * VEXT_ + ext[(size_t)b * LIN_ + l]],
              q * am[(size_t)row * LIN_ + l]);
}

// ---------------------------------------------------------------------------
static inline void gemm(const float* A, const float* W, const float* bias,
                        const float* rowscale, float* C,
                        int M, int N, int K, int ldc, int relu) {
    if (M > 2048) {
        dim3 grid(N / 128, (M + 127) / 128);
        gemm_tf32<4><<<grid, 256>>>(A, W, bias, rowscale, C, M, N, K, ldc, relu);
    } else {
        dim3 grid(N / 128, (M + 63) / 64);
        gemm_tf32<2><<<grid, 256>>>(A, W, bias, rowscale, C, M, N, K, ldc, relu);
    }
}

extern "C" void kernel_launch(void* const* d_in, const int* in_sizes, int n_in,
                              void* d_out, int out_size) {
    const int*   inp     = (const int*)d_in[0];
    const int*   tar     = (const int*)d_in[1];
    const int*   ext     = (const int*)d_in[2];
    const float* enc_pad = (const float*)d_in[3];
    const float* look    = (const float*)d_in[4];
    const float* dec_pad = (const float*)d_in[5];
    int o = (in_sizes[6] <= 4) ? 7 : 6;
    const float* emb_enc = (const float*)d_in[o + 0];
    const float* emb_dec = (const float*)d_in[o + 1];
    const float* eaw  = (const float*)d_in[o + 2];
    const float* eab  = (const float*)d_in[o + 3];
    const float* ew1  = (const float*)d_in[o + 4];
    const float* eb1  = (const float*)d_in[o + 5];
    const float* ew2  = (const float*)d_in[o + 6];
    const float* eb2  = (const float*)d_in[o + 7];
    const float* elng = (const float*)d_in[o + 8];
    const float* elnb = (const float*)d_in[o + 9];
    const float* daw  = (const float*)d_in[o + 10];
    const float* dab  = (const float*)d_in[o + 11];
    const float* dw1  = (const float*)d_in[o + 12];
    const float* db1  = (const float*)d_in[o + 13];
    const float* dw2  = (const float*)d_in[o + 14];
    const float* db2  = (const float*)d_in[o + 15];
    const float* dlng = (const float*)d_in[o + 16];
    const float* dlnb = (const float*)d_in[o + 17];
    const float* ptrw = (const float*)d_in[o + 18];
    const float* ptrb = (const float*)d_in[o + 19];
    const float* finw = (const float*)d_in[o + 20];
    const float* finb = (const float*)d_in[o + 21];
    float* out = (float*)d_out;

    float *pe, *encx, *q, *k, *v, *attno, *tmp, *ffn, *decx, *o1buf,
          *embedr, *block2, *ctx, *pg;
    cudaGetSymbolAddress((void**)&pe,     g_pe);
    cudaGetSymbolAddress((void**)&encx,   g_encx);
    cudaGetSymbolAddress((void**)&q,      g_q);
    cudaGetSymbolAddress((void**)&k,      g_k);
    cudaGetSymbolAddress((void**)&v,      g_v);
    cudaGetSymbolAddress((void**)&attno,  g_attno);
    cudaGetSymbolAddress((void**)&tmp,    g_tmp);
    cudaGetSymbolAddress((void**)&ffn,    g_ffn);
    cudaGetSymbolAddress((void**)&decx,   g_decx);
    cudaGetSymbolAddress((void**)&o1buf,  g_o1);
    cudaGetSymbolAddress((void**)&embedr, g_embed);
    cudaGetSymbolAddress((void**)&block2, g_block2);
    cudaGetSymbolAddress((void**)&ctx,    g_ctx);
    cudaGetSymbolAddress((void**)&pg,     g_pg);

    const int ME = B_ * LIN_;  // 6400
    const int MD = B_ * T_;    // 1600

    pe_kernel<<<(LIN_ * D_ + 255) / 256, 256>>>(pe);
    embed_kernel<<<(ME * D_ + 255) / 256, 256>>>(inp, emb_enc, pe, encx,
                                                 nullptr, LIN_, ME * D_);
    embed_kernel<<<(MD * D_ + 255) / 256, 256>>>(tar, emb_dec, pe, decx,
                                                 embedr, T_, MD * D_);

    // ----- encoder -----
    for (int i = 0; i < L_; i++) {
        const float* w  = eaw + (size_t)i * 4 * D_ * D_;
        const float* bb = eab + (size_t)i * 4 * D_;
        gemm(encx, w + 0 * D_ * D_, bb + 0 * D_, nullptr, q, ME, D_, D_, D_, 0);
        gemm(encx, w + 1 * D_ * D_, bb + 1 * D_, nullptr, k, ME, D_, D_, D_, 0);
        gemm(encx, w + 2 * D_ * D_, bb + 2 * D_, nullptr, v, ME, D_, D_, D_, 0);
        attn_tiled<<<B_ * H_ * ((LIN_ + 15) / 16), 128>>>(
            q, k, v, enc_pad, 0, attno, nullptr, nullptr, nullptr, LIN_, LIN_);
        gemm(attno, w + 3 * D_ * D_, bb + 3 * D_, nullptr, tmp, ME, D_, D_, D_, 0);
        add_ln<<<ME, 128>>>(encx, tmp, elng + (size_t)(i * 2 + 0) * D_,
                            elnb + (size_t)(i * 2 + 0) * D_, encx);
        gemm(encx, ew1 + (size_t)i * D_ * DFF_, eb1 + (size_t)i * DFF_,
             nullptr, ffn, ME, DFF_, D_, DFF_, 1);
        gemm(ffn, ew2 + (size_t)i * DFF_ * D_, eb2 + (size_t)i * D_,
             nullptr, tmp, ME, D_, DFF_, D_, 0);
        add_ln<<<ME, 128>>>(encx, tmp, elng + (size_t)(i * 2 + 1) * D_,
                            elnb + (size_t)(i * 2 + 1) * D_, encx);
    }

    // ----- decoder: only layer L-1 affects outputs (reference never feeds
    // dec_out back into xd) -----
    {
        const int i = L_ - 1;
        const float* w0 = daw + (size_t)(i * 2 + 0) * 4 * D_ * D_;
        const float* b0 = dab + (size_t)(i * 2 + 0) * 4 * D_;
        gemm(decx, w0 + 0 * D_ * D_, b0 + 0 * D_, nullptr, q, MD, D_, D_, D_, 0);
        gemm(decx, w0 + 1 * D_ * D_, b0 + 1 * D_, nullptr, k, MD, D_, D_, D_, 0);
        gemm(decx, w0 + 2 * D_ * D_, b0 + 2 * D_, nullptr, v, MD, D_, D_, D_, 0);
        attn_tiled<<<B_ * H_ * ((T_ + 15) / 16), 128>>>(
            q, k, v, look, 1, attno, nullptr, nullptr, nullptr, T_, T_);
        gemm(attno, w0 + 3 * D_ * D_, b0 + 3 * D_, nullptr, tmp, MD, D_, D_, D_, 0);
        add_ln<<<MD, 128>>>(decx, tmp, dlng + (size_t)(i * 3 + 0) * D_,
                            dlnb + (size_t)(i * 3 + 0) * D_, o1buf);
        // cross-attention; also fuses context = P @ enc_heads
        const float* w1 = daw + (size_t)(i * 2 + 1) * 4 * D_ * D_;
        const float* b1 = dab + (size_t)(i * 2 + 1) * 4 * D_;
        gemm(o1buf, w1 + 0 * D_ * D_, b1 + 0 * D_, nullptr, q, MD, D_, D_, D_, 0);
        gemm(encx, w1 + 1 * D_ * D_, b1 + 1 * D_, nullptr, k, ME, D_, D_, D_, 0);
        gemm(encx, w1 + 2 * D_ * D_, b1 + 2 * D_, nullptr, v, ME, D_, D_, D_, 0);
        attn_tiled<<<B_ * H_ * ((T_ + 15) / 16), 128>>>(
            q, k, v, dec_pad, 0, attno, block2, encx, ctx, T_, LIN_);
        gemm(attno, w1 + 3 * D_ * D_, b1 + 3 * D_, nullptr, tmp, MD, D_, D_, D_, 0);
        add_ln<<<MD, 128>>>(o1buf, tmp, dlng + (size_t)(i * 3 + 1) * D_,
                            dlnb + (size_t)(i * 3 + 1) * D_, o1buf);
        gemm(o1buf, dw1 + (size_t)i * D_ * DFF_, db1 + (size_t)i * DFF_,
             nullptr, ffn, MD, DFF_, D_, DFF_, 1);
        gemm(ffn, dw2 + (size_t)i * DFF_ * D_, db2 + (size_t)i * D_,
             nullptr, tmp, MD, D_, DFF_, D_, 0);
        add_ln<<<MD, 128>>>(o1buf, tmp, dlng + (size_t)(i * 3 + 2) * D_,
                            dlnb + (size_t)(i * 3 + 2) * D_, decx);
    }

    // ----- pointer-generator prob, then head with fused p*logits -----
    pgen_kernel<<<MD, 128>>>(ctx, decx, embedr, ptrw, ptrb, pg);
    gemm(decx, finw, finb, pg, out, MD, V_, D_, VEXT_, 0);
    zero_tail_kernel<<<(MD * 100 + 255) / 256, 256>>>(out);

    float* out2 = out + (size_t)MD * VEXT_;
    attn_mean_kernel<<<MD, 128>>>(block2, out2);
    scatter_kernel<<<(B_ * T_ * LIN_ + 255) / 256, 256>>>(out, out2, pg, ext);
}